// round 15
// baseline (speedup 1.0000x reference)
#include <cuda_runtime.h>
#include <cuda_fp16.h>
#include <mma.h>
using namespace nvcuda;

#define N_NODES 100000
#define D 128
#define N_ADJ 6
#define NNZ 600000
#define TOTAL_E (N_ADJ * NNZ)
#define N_HOPS 7

// multi-block scan geometry: 25 blocks x 1024 threads x 4 elems = 102400 >= 100000
#define SCAN_T 1024
#define SCAN_ELEMS (SCAN_T * 4)
#define SCAN_B ((N_NODES + SCAN_ELEMS - 1) / SCAN_ELEMS)

// ---------------- device scratch (static, no allocations) ----------------
__device__ float  g_mix[N_HOPS];
__device__ int    g_count[N_NODES];
__device__ int    g_offsets[N_NODES + 1];
__device__ int    g_cursor[N_NODES];
__device__ int    g_bsum[SCAN_B];
__device__ int    g_bpre[SCAN_B];
__device__ int2   g_edges[TOTAL_E];            // (col, weight-as-int) per edge, CSR order
__device__ __half g_inph[(size_t)N_NODES * D]; // fp16 copy of input for gather
__device__ __half g_reph[((size_t)N_NODES + 64) * D]; // fp16 rep for tensor GEMM (+pad rows)
__device__ __half g_Wh[D * D];                 // fp16 copy of weight
__device__ float  g_rep[(size_t)N_NODES * D];  // fallback if d_out lacks rep slot

// ---------------- softmax of mixing weights ----------------
__global__ void mix_kernel(const float* __restrict__ lw) {
    if (threadIdx.x == 0) {
        float m = -1e30f;
        #pragma unroll
        for (int i = 0; i < N_HOPS; i++) m = fmaxf(m, lw[i]);
        float e[N_HOPS];
        float s = 0.f;
        #pragma unroll
        for (int i = 0; i < N_HOPS; i++) { e[i] = expf(lw[i] - m); s += e[i]; }
        float inv = 1.f / s;
        #pragma unroll
        for (int i = 0; i < N_HOPS; i++) g_mix[i] = e[i] * inv;
    }
}

// ---------------- fp32 -> fp16 copies: input and weight ----------------
__global__ void tohalf_kernel(const float4* __restrict__ in, const float4* __restrict__ W) {
    int i = blockIdx.x * blockDim.x + threadIdx.x;  // over N*D/4
    if (i < N_NODES * D / 4) {
        float4 v = in[i];
        __half2 h0 = __floats2half2_rn(v.x, v.y);
        __half2 h1 = __floats2half2_rn(v.z, v.w);
        uint2 u;
        u.x = *reinterpret_cast<unsigned*>(&h0);
        u.y = *reinterpret_cast<unsigned*>(&h1);
        reinterpret_cast<uint2*>(g_inph)[i] = u;
    }
    if (i < D * D / 4) {   // weight: 16384 elems = 4096 float4
        float4 v = W[i];
        __half2 h0 = __floats2half2_rn(v.x, v.y);
        __half2 h1 = __floats2half2_rn(v.z, v.w);
        uint2 u;
        u.x = *reinterpret_cast<unsigned*>(&h0);
        u.y = *reinterpret_cast<unsigned*>(&h1);
        reinterpret_cast<uint2*>(g_Wh)[i] = u;
    }
}

// ---------------- CSR build ----------------
__global__ void hist_kernel(const int* __restrict__ rows) {
    int e = blockIdx.x * blockDim.x + threadIdx.x;
    if (e < TOTAL_E) atomicAdd(&g_count[rows[e]], 1);
}

// pass 1: per-block totals
__global__ __launch_bounds__(SCAN_T) void scan_pass1() {
    __shared__ int warp_sums[32];
    int t = threadIdx.x;
    int lane = t & 31, wid = t >> 5;
    int idx = blockIdx.x * SCAN_ELEMS + t * 4;

    int local = 0;
    if (idx + 3 < N_NODES) {
        int4 c = *reinterpret_cast<const int4*>(g_count + idx);
        local = c.x + c.y + c.z + c.w;
    } else {
        for (int j = 0; j < 4; j++)
            if (idx + j < N_NODES) local += g_count[idx + j];
    }
    #pragma unroll
    for (int d = 16; d > 0; d >>= 1) local += __shfl_down_sync(0xffffffffu, local, d);
    if (lane == 0) warp_sums[wid] = local;
    __syncthreads();
    if (wid == 0) {
        int v = warp_sums[lane];
        #pragma unroll
        for (int d = 16; d > 0; d >>= 1) v += __shfl_down_sync(0xffffffffu, v, d);
        if (lane == 0) g_bsum[blockIdx.x] = v;
    }
}

// pass 2: exclusive scan of SCAN_B block sums (one warp)
__global__ void scan_pass2() {
    int lane = threadIdx.x;
    int v = (lane < SCAN_B) ? g_bsum[lane] : 0;
    int inc = v;
    #pragma unroll
    for (int d = 1; d < 32; d <<= 1) {
        int n = __shfl_up_sync(0xffffffffu, inc, d);
        if (lane >= d) inc += n;
    }
    if (lane < SCAN_B) g_bpre[lane] = inc - v;   // exclusive
    if (lane == 0) g_offsets[N_NODES] = TOTAL_E;
}

// pass 3: full scan within each block + block prefix -> offsets & cursors
__global__ __launch_bounds__(SCAN_T) void scan_pass3() {
    __shared__ int warp_sums[32];
    int t = threadIdx.x;
    int lane = t & 31, wid = t >> 5;
    int idx = blockIdx.x * SCAN_ELEMS + t * 4;

    int4 c = make_int4(0, 0, 0, 0);
    if (idx + 3 < N_NODES) {
        c = *reinterpret_cast<const int4*>(g_count + idx);
    } else {
        if (idx + 0 < N_NODES) c.x = g_count[idx + 0];
        if (idx + 1 < N_NODES) c.y = g_count[idx + 1];
        if (idx + 2 < N_NODES) c.z = g_count[idx + 2];
        if (idx + 3 < N_NODES) c.w = g_count[idx + 3];
    }
    int local = c.x + c.y + c.z + c.w;

    int v = local;
    #pragma unroll
    for (int d = 1; d < 32; d <<= 1) {
        int n = __shfl_up_sync(0xffffffffu, v, d);
        if (lane >= d) v += n;
    }
    if (lane == 31) warp_sums[wid] = v;
    __syncthreads();
    if (wid == 0) {
        int w = warp_sums[lane];
        #pragma unroll
        for (int d = 1; d < 32; d <<= 1) {
            int n = __shfl_up_sync(0xffffffffu, w, d);
            if (lane >= d) w += n;
        }
        warp_sums[lane] = w;
    }
    __syncthreads();

    int warp_prefix = (wid > 0) ? warp_sums[wid - 1] : 0;
    int excl = g_bpre[blockIdx.x] + warp_prefix + (v - local);
    int o0 = excl;
    int o1 = o0 + c.x;
    int o2 = o1 + c.y;
    int o3 = o2 + c.z;
    if (idx + 0 < N_NODES) { g_offsets[idx + 0] = o0; g_cursor[idx + 0] = o0; }
    if (idx + 1 < N_NODES) { g_offsets[idx + 1] = o1; g_cursor[idx + 1] = o1; }
    if (idx + 2 < N_NODES) { g_offsets[idx + 2] = o2; g_cursor[idx + 2] = o2; }
    if (idx + 3 < N_NODES) { g_offsets[idx + 3] = o3; g_cursor[idx + 3] = o3; }
}

__global__ void fill_kernel(const int* __restrict__ rows,
                            const int* __restrict__ cols,
                            const float* __restrict__ vals) {
    int e = blockIdx.x * blockDim.x + threadIdx.x;
    if (e >= TOTAL_E) return;
    int a = e / NNZ;
    int r = rows[e];
    int c = cols[e];
    float w = g_mix[a + 1] * vals[e];
    int slot = atomicAdd(&g_cursor[r], 1);
    g_edges[slot] = make_int2(c, __float_as_int(w));
}

// ---------------- gather: one warp per row; fp16 neighbors, fp32 acc ----------------
// rep[r,:] = mix0*input_f32[r,:] + sum_{e in row r} w_e * input_f16[col_e,:]
// also emits fp16 rep row for the tensor GEMM
__device__ __forceinline__ void gacc(float4& acc, float w, uint2 u) {
    __half2 h0 = *reinterpret_cast<__half2*>(&u.x);
    __half2 h1 = *reinterpret_cast<__half2*>(&u.y);
    float2 f0 = __half22float2(h0);
    float2 f1 = __half22float2(h1);
    acc.x = fmaf(w, f0.x, acc.x);
    acc.y = fmaf(w, f0.y, acc.y);
    acc.z = fmaf(w, f1.x, acc.z);
    acc.w = fmaf(w, f1.y, acc.w);
}

__global__ __launch_bounds__(256) void gather_kernel(const float* __restrict__ input,
                                                     float* __restrict__ rep) {
    int gw = (blockIdx.x * blockDim.x + threadIdx.x) >> 5;  // global warp = row
    int lane = threadIdx.x & 31;
    if (gw >= N_NODES) return;
    int row = gw;

    float m0 = g_mix[0];
    float4 acc = reinterpret_cast<const float4*>(input + (size_t)row * D)[lane];
    acc.x *= m0; acc.y *= m0; acc.z *= m0; acc.w *= m0;

    int beg = g_offsets[row];
    int end = g_offsets[row + 1];
    int e = beg;
    for (; e + 4 <= end; e += 4) {
        int2 e0 = __ldg(g_edges + e + 0);
        int2 e1 = __ldg(g_edges + e + 1);
        int2 e2 = __ldg(g_edges + e + 2);
        int2 e3 = __ldg(g_edges + e + 3);
        uint2 u0 = __ldg(reinterpret_cast<const uint2*>(g_inph + (size_t)e0.x * D) + lane);
        uint2 u1 = __ldg(reinterpret_cast<const uint2*>(g_inph + (size_t)e1.x * D) + lane);
        uint2 u2 = __ldg(reinterpret_cast<const uint2*>(g_inph + (size_t)e2.x * D) + lane);
        uint2 u3 = __ldg(reinterpret_cast<const uint2*>(g_inph + (size_t)e3.x * D) + lane);
        gacc(acc, __int_as_float(e0.y), u0);
        gacc(acc, __int_as_float(e1.y), u1);
        gacc(acc, __int_as_float(e2.y), u2);
        gacc(acc, __int_as_float(e3.y), u3);
    }
    for (; e < end; e++) {
        int2 ed = __ldg(g_edges + e);
        uint2 u = __ldg(reinterpret_cast<const uint2*>(g_inph + (size_t)ed.x * D) + lane);
        gacc(acc, __int_as_float(ed.y), u);
    }
    reinterpret_cast<float4*>(rep + (size_t)row * D)[lane] = acc;

    // fp16 copy for tensor GEMM
    __half2 h0 = __floats2half2_rn(acc.x, acc.y);
    __half2 h1 = __floats2half2_rn(acc.z, acc.w);
    uint2 uo;
    uo.x = *reinterpret_cast<unsigned*>(&h0);
    uo.y = *reinterpret_cast<unsigned*>(&h1);
    reinterpret_cast<uint2*>(g_reph + (size_t)row * D)[lane] = uo;
}

// ---------------- out = rep_f16 @ W_f16 + bias  (wmma, fp32 accumulate) ----------------
// Block: 256 threads = 8 warps, tile 64 rows x 128 cols.
// Warp w: rows [(w&3)*16, +16), cols [(w>>2)*64, +64) -> 4 accumulator frags.
__global__ __launch_bounds__(256) void gemm_wmma(const float* __restrict__ bias,
                                                 float* __restrict__ out) {
    __shared__ float Cs[8][16][64];  // 32KB, per-warp staging for bias add

    int w = threadIdx.x >> 5;
    int lane = threadIdx.x & 31;
    int rowBase = blockIdx.x * 64 + (w & 3) * 16;
    int colBase = (w >> 2) * 64;

    wmma::fragment<wmma::accumulator, 16, 16, 16, float> acc[4];
    #pragma unroll
    for (int j = 0; j < 4; j++) wmma::fill_fragment(acc[j], 0.f);
    wmma::fragment<wmma::matrix_a, 16, 16, 16, __half, wmma::row_major> af;
    wmma::fragment<wmma::matrix_b, 16, 16, 16, __half, wmma::row_major> bf;

    #pragma unroll
    for (int k = 0; k < D / 16; k++) {
        wmma::load_matrix_sync(af, g_reph + (size_t)rowBase * D + k * 16, D);
        #pragma unroll
        for (int j = 0; j < 4; j++) {
            wmma::load_matrix_sync(bf, g_Wh + (k * 16) * D + colBase + j * 16, D);
            wmma::mma_sync(acc[j], af, bf, acc[j]);
        }
    }

    #pragma unroll
    for (int j = 0; j < 4; j++)
        wmma::store_matrix_sync(&Cs[w][0][j * 16], acc[j], 64, wmma::mem_row_major);
    __syncwarp();

    // lane -> row r = lane/2, col half cs = (lane&1)*32 : 8 float4 per lane
    int r = lane >> 1;
    int cs = (lane & 1) * 32;
    int grow = rowBase + r;
    if (grow < N_NODES) {
        float* dst = out + (size_t)grow * D + colBase + cs;
        #pragma unroll
        for (int q = 0; q < 8; q++) {
            float4 v = *reinterpret_cast<float4*>(&Cs[w][r][cs + q * 4]);
            float4 bv = *reinterpret_cast<const float4*>(bias + colBase + cs + q * 4);
            v.x += bv.x; v.y += bv.y; v.z += bv.z; v.w += bv.w;
            reinterpret_cast<float4*>(dst)[q] = v;
        }
    }
}

extern "C" void kernel_launch(void* const* d_in, const int* in_sizes, int n_in,
                              void* d_out, int out_size) {
    const float* input   = (const float*)d_in[0];
    const int*   adjrows = (const int*)d_in[1];   // jnp int64 -> int32 (x64 off)
    const int*   adjcols = (const int*)d_in[2];
    const float* adjvals = (const float*)d_in[3];
    const float* weight  = (const float*)d_in[4];
    const float* linw    = (const float*)d_in[5];
    const float* bias    = (const float*)d_in[6];

    float* out = (float*)d_out;  // [N_NODES, D]
    float* rep;
    if ((long long)out_size >= 2LL * N_NODES * D) {
        rep = out + (size_t)N_NODES * D;
    } else {
        cudaGetSymbolAddress((void**)&rep, g_rep);
    }

    mix_kernel<<<1, 32>>>(linw);

    void* countPtr = nullptr;
    cudaGetSymbolAddress(&countPtr, g_count);
    cudaMemsetAsync(countPtr, 0, N_NODES * sizeof(int));

    tohalf_kernel<<<(N_NODES * D / 4 + 255) / 256, 256>>>((const float4*)input,
                                                          (const float4*)weight);

    hist_kernel<<<(TOTAL_E + 255) / 256, 256>>>(adjrows);
    scan_pass1<<<SCAN_B, SCAN_T>>>();
    scan_pass2<<<1, 32>>>();
    scan_pass3<<<SCAN_B, SCAN_T>>>();
    fill_kernel<<<(TOTAL_E + 255) / 256, 256>>>(adjrows, adjcols, adjvals);

    // one warp per row
    long long gthreads = (long long)N_NODES * 32;
    gather_kernel<<<(int)((gthreads + 255) / 256), 256>>>(input, rep);

    gemm_wmma<<<(N_NODES + 63) / 64, 256>>>(bias, out);
}

// round 16
// speedup vs baseline: 1.8211x; 1.8211x over previous
#include <cuda_runtime.h>
#include <cuda_fp16.h>
#include <mma.h>
using namespace nvcuda;

#define N_NODES 100000
#define D 128
#define N_ADJ 6
#define NNZ 600000
#define TOTAL_E (N_ADJ * NNZ)
#define N_HOPS 7
#define SPAD 144   // smem row width in halves (128 + 16): 288B rows, 32B-aligned frag ptrs

// multi-block scan geometry: 25 blocks x 1024 threads x 4 elems = 102400 >= 100000
#define SCAN_T 1024
#define SCAN_ELEMS (SCAN_T * 4)
#define SCAN_B ((N_NODES + SCAN_ELEMS - 1) / SCAN_ELEMS)

// ---------------- device scratch (static, no allocations) ----------------
__device__ float  g_mix[N_HOPS];
__device__ int    g_count[N_NODES];
__device__ int    g_offsets[N_NODES + 1];
__device__ int    g_cursor[N_NODES];
__device__ int    g_bsum[SCAN_B];
__device__ int    g_bpre[SCAN_B];
__device__ int2   g_edges[TOTAL_E];            // (col, weight-as-int) per edge, CSR order
__device__ __half g_inph[(size_t)N_NODES * D]; // fp16 copy of input for gather
__device__ __half g_reph[((size_t)N_NODES + 64) * D]; // fp16 rep (+pad rows, zero-init)
__device__ __half g_Wh[D * D];                 // fp16 copy of weight
__device__ float  g_biasrep[16 * D];           // bias replicated over 16 rows (acc init)
__device__ float  g_rep[(size_t)N_NODES * D];  // fallback if d_out lacks rep slot

// ---------------- softmax of mixing weights ----------------
__global__ void mix_kernel(const float* __restrict__ lw) {
    if (threadIdx.x == 0) {
        float m = -1e30f;
        #pragma unroll
        for (int i = 0; i < N_HOPS; i++) m = fmaxf(m, lw[i]);
        float e[N_HOPS];
        float s = 0.f;
        #pragma unroll
        for (int i = 0; i < N_HOPS; i++) { e[i] = expf(lw[i] - m); s += e[i]; }
        float inv = 1.f / s;
        #pragma unroll
        for (int i = 0; i < N_HOPS; i++) g_mix[i] = e[i] * inv;
    }
}

// ---------------- fp32 -> fp16 copies: input, weight; bias replication ----------------
__global__ void tohalf_kernel(const float4* __restrict__ in, const float4* __restrict__ W,
                              const float* __restrict__ bias) {
    int i = blockIdx.x * blockDim.x + threadIdx.x;  // over N*D/4
    if (i < N_NODES * D / 4) {
        float4 v = in[i];
        __half2 h0 = __floats2half2_rn(v.x, v.y);
        __half2 h1 = __floats2half2_rn(v.z, v.w);
        uint2 u;
        u.x = *reinterpret_cast<unsigned*>(&h0);
        u.y = *reinterpret_cast<unsigned*>(&h1);
        reinterpret_cast<uint2*>(g_inph)[i] = u;
    }
    if (i < D * D / 4) {   // weight: 16384 elems = 4096 float4
        float4 v = W[i];
        __half2 h0 = __floats2half2_rn(v.x, v.y);
        __half2 h1 = __floats2half2_rn(v.z, v.w);
        uint2 u;
        u.x = *reinterpret_cast<unsigned*>(&h0);
        u.y = *reinterpret_cast<unsigned*>(&h1);
        reinterpret_cast<uint2*>(g_Wh)[i] = u;
    }
    if (i < 16 * D) {      // bias replicated across 16 rows for acc init
        g_biasrep[i] = bias[i & (D - 1)];
    }
}

// ---------------- CSR build ----------------
__global__ void hist_kernel(const int* __restrict__ rows) {
    int e = blockIdx.x * blockDim.x + threadIdx.x;
    if (e < TOTAL_E) atomicAdd(&g_count[rows[e]], 1);
}

// pass 1: per-block totals
__global__ __launch_bounds__(SCAN_T) void scan_pass1() {
    __shared__ int warp_sums[32];
    int t = threadIdx.x;
    int lane = t & 31, wid = t >> 5;
    int idx = blockIdx.x * SCAN_ELEMS + t * 4;

    int local = 0;
    if (idx + 3 < N_NODES) {
        int4 c = *reinterpret_cast<const int4*>(g_count + idx);
        local = c.x + c.y + c.z + c.w;
    } else {
        for (int j = 0; j < 4; j++)
            if (idx + j < N_NODES) local += g_count[idx + j];
    }
    #pragma unroll
    for (int d = 16; d > 0; d >>= 1) local += __shfl_down_sync(0xffffffffu, local, d);
    if (lane == 0) warp_sums[wid] = local;
    __syncthreads();
    if (wid == 0) {
        int v = warp_sums[lane];
        #pragma unroll
        for (int d = 16; d > 0; d >>= 1) v += __shfl_down_sync(0xffffffffu, v, d);
        if (lane == 0) g_bsum[blockIdx.x] = v;
    }
}

// pass 2: exclusive scan of SCAN_B block sums (one warp)
__global__ void scan_pass2() {
    int lane = threadIdx.x;
    int v = (lane < SCAN_B) ? g_bsum[lane] : 0;
    int inc = v;
    #pragma unroll
    for (int d = 1; d < 32; d <<= 1) {
        int n = __shfl_up_sync(0xffffffffu, inc, d);
        if (lane >= d) inc += n;
    }
    if (lane < SCAN_B) g_bpre[lane] = inc - v;   // exclusive
    if (lane == 0) g_offsets[N_NODES] = TOTAL_E;
}

// pass 3: full scan within each block + block prefix -> offsets & cursors
__global__ __launch_bounds__(SCAN_T) void scan_pass3() {
    __shared__ int warp_sums[32];
    int t = threadIdx.x;
    int lane = t & 31, wid = t >> 5;
    int idx = blockIdx.x * SCAN_ELEMS + t * 4;

    int4 c = make_int4(0, 0, 0, 0);
    if (idx + 3 < N_NODES) {
        c = *reinterpret_cast<const int4*>(g_count + idx);
    } else {
        if (idx + 0 < N_NODES) c.x = g_count[idx + 0];
        if (idx + 1 < N_NODES) c.y = g_count[idx + 1];
        if (idx + 2 < N_NODES) c.z = g_count[idx + 2];
        if (idx + 3 < N_NODES) c.w = g_count[idx + 3];
    }
    int local = c.x + c.y + c.z + c.w;

    int v = local;
    #pragma unroll
    for (int d = 1; d < 32; d <<= 1) {
        int n = __shfl_up_sync(0xffffffffu, v, d);
        if (lane >= d) v += n;
    }
    if (lane == 31) warp_sums[wid] = v;
    __syncthreads();
    if (wid == 0) {
        int w = warp_sums[lane];
        #pragma unroll
        for (int d = 1; d < 32; d <<= 1) {
            int n = __shfl_up_sync(0xffffffffu, w, d);
            if (lane >= d) w += n;
        }
        warp_sums[lane] = w;
    }
    __syncthreads();

    int warp_prefix = (wid > 0) ? warp_sums[wid - 1] : 0;
    int excl = g_bpre[blockIdx.x] + warp_prefix + (v - local);
    int o0 = excl;
    int o1 = o0 + c.x;
    int o2 = o1 + c.y;
    int o3 = o2 + c.z;
    if (idx + 0 < N_NODES) { g_offsets[idx + 0] = o0; g_cursor[idx + 0] = o0; }
    if (idx + 1 < N_NODES) { g_offsets[idx + 1] = o1; g_cursor[idx + 1] = o1; }
    if (idx + 2 < N_NODES) { g_offsets[idx + 2] = o2; g_cursor[idx + 2] = o2; }
    if (idx + 3 < N_NODES) { g_offsets[idx + 3] = o3; g_cursor[idx + 3] = o3; }
}

__global__ void fill_kernel(const int* __restrict__ rows,
                            const int* __restrict__ cols,
                            const float* __restrict__ vals) {
    int e = blockIdx.x * blockDim.x + threadIdx.x;
    if (e >= TOTAL_E) return;
    int a = e / NNZ;
    int r = rows[e];
    int c = cols[e];
    float w = g_mix[a + 1] * vals[e];
    int slot = atomicAdd(&g_cursor[r], 1);
    g_edges[slot] = make_int2(c, __float_as_int(w));
}

// ---------------- gather: one warp per row; fp16 neighbors, fp32 acc ----------------
__device__ __forceinline__ void gacc(float4& acc, float w, uint2 u) {
    __half2 h0 = *reinterpret_cast<__half2*>(&u.x);
    __half2 h1 = *reinterpret_cast<__half2*>(&u.y);
    float2 f0 = __half22float2(h0);
    float2 f1 = __half22float2(h1);
    acc.x = fmaf(w, f0.x, acc.x);
    acc.y = fmaf(w, f0.y, acc.y);
    acc.z = fmaf(w, f1.x, acc.z);
    acc.w = fmaf(w, f1.y, acc.w);
}

__global__ __launch_bounds__(256) void gather_kernel(const float* __restrict__ input,
                                                     float* __restrict__ rep) {
    int gw = (blockIdx.x * blockDim.x + threadIdx.x) >> 5;  // global warp = row
    int lane = threadIdx.x & 31;
    if (gw >= N_NODES) return;
    int row = gw;

    float m0 = g_mix[0];
    float4 acc = reinterpret_cast<const float4*>(input + (size_t)row * D)[lane];
    acc.x *= m0; acc.y *= m0; acc.z *= m0; acc.w *= m0;

    int beg = g_offsets[row];
    int end = g_offsets[row + 1];
    int e = beg;
    for (; e + 4 <= end; e += 4) {
        int2 e0 = __ldg(g_edges + e + 0);
        int2 e1 = __ldg(g_edges + e + 1);
        int2 e2 = __ldg(g_edges + e + 2);
        int2 e3 = __ldg(g_edges + e + 3);
        uint2 u0 = __ldg(reinterpret_cast<const uint2*>(g_inph + (size_t)e0.x * D) + lane);
        uint2 u1 = __ldg(reinterpret_cast<const uint2*>(g_inph + (size_t)e1.x * D) + lane);
        uint2 u2 = __ldg(reinterpret_cast<const uint2*>(g_inph + (size_t)e2.x * D) + lane);
        uint2 u3 = __ldg(reinterpret_cast<const uint2*>(g_inph + (size_t)e3.x * D) + lane);
        gacc(acc, __int_as_float(e0.y), u0);
        gacc(acc, __int_as_float(e1.y), u1);
        gacc(acc, __int_as_float(e2.y), u2);
        gacc(acc, __int_as_float(e3.y), u3);
    }
    for (; e < end; e++) {
        int2 ed = __ldg(g_edges + e);
        uint2 u = __ldg(reinterpret_cast<const uint2*>(g_inph + (size_t)ed.x * D) + lane);
        gacc(acc, __int_as_float(ed.y), u);
    }
    reinterpret_cast<float4*>(rep + (size_t)row * D)[lane] = acc;

    // fp16 copy for tensor GEMM
    __half2 h0 = __floats2half2_rn(acc.x, acc.y);
    __half2 h1 = __floats2half2_rn(acc.z, acc.w);
    uint2 uo;
    uo.x = *reinterpret_cast<unsigned*>(&h0);
    uo.y = *reinterpret_cast<unsigned*>(&h1);
    reinterpret_cast<uint2*>(g_reph + (size_t)row * D)[lane] = uo;
}

// ---------------- out = rep_f16 @ W_f16 + bias  (wmma, smem-staged) ----------------
// Block: 256 threads = 8 warps, tile 64 rows x 128 cols.
// Warp w: rows rowBase+(w&3)*16, cols (w>>2)*64 -> 4 acc frags, init from bias table.
__global__ __launch_bounds__(256) void gemm_wmma(float* __restrict__ out) {
    __shared__ __half Ws[D][SPAD];   // 128 x 144 halves = 36.9KB
    __shared__ __half As[64][SPAD];  // 64 x 144 halves = 18.4KB

    int tid = threadIdx.x;
    int w = tid >> 5;
    int rowBase = blockIdx.x * 64;

    // stage W (full 128x128) : 2048 uint4, 8 per thread
    #pragma unroll
    for (int l = 0; l < 8; l++) {
        int i = tid + l * 256;
        int r = i >> 4;
        int c8 = (i & 15) * 8;
        uint4 v = *reinterpret_cast<const uint4*>(&g_Wh[r * D + c8]);
        *reinterpret_cast<uint4*>(&Ws[r][c8]) = v;
    }
    // stage A tile (64x128): 1024 uint4, 4 per thread (pad rows in g_reph are zero)
    #pragma unroll
    for (int l = 0; l < 4; l++) {
        int i = tid + l * 256;
        int r = i >> 4;
        int c8 = (i & 15) * 8;
        uint4 v = *reinterpret_cast<const uint4*>(&g_reph[(size_t)(rowBase + r) * D + c8]);
        *reinterpret_cast<uint4*>(&As[r][c8]) = v;
    }
    __syncthreads();

    int rLoc = (w & 3) * 16;
    int colBase = (w >> 2) * 64;
    if (rowBase + rLoc + 16 <= N_NODES) {  // N_NODES % 16 == 0: frag fully in or out
        wmma::fragment<wmma::accumulator, 16, 16, 16, float> acc[4];
        #pragma unroll
        for (int j = 0; j < 4; j++)
            wmma::load_matrix_sync(acc[j], g_biasrep + colBase + j * 16, D,
                                   wmma::mem_row_major);

        wmma::fragment<wmma::matrix_a, 16, 16, 16, __half, wmma::row_major> af;
        wmma::fragment<wmma::matrix_b, 16, 16, 16, __half, wmma::row_major> bf;
        #pragma unroll
        for (int k = 0; k < D / 16; k++) {
            wmma::load_matrix_sync(af, &As[rLoc][k * 16], SPAD);
            #pragma unroll
            for (int j = 0; j < 4; j++) {
                wmma::load_matrix_sync(bf, &Ws[k * 16][colBase + j * 16], SPAD);
                wmma::mma_sync(acc[j], af, bf, acc[j]);
            }
        }
        #pragma unroll
        for (int j = 0; j < 4; j++)
            wmma::store_matrix_sync(out + (size_t)(rowBase + rLoc) * D + colBase + j * 16,
                                    acc[j], D, wmma::mem_row_major);
    }
}

extern "C" void kernel_launch(void* const* d_in, const int* in_sizes, int n_in,
                              void* d_out, int out_size) {
    const float* input   = (const float*)d_in[0];
    const int*   adjrows = (const int*)d_in[1];   // jnp int64 -> int32 (x64 off)
    const int*   adjcols = (const int*)d_in[2];
    const float* adjvals = (const float*)d_in[3];
    const float* weight  = (const float*)d_in[4];
    const float* linw    = (const float*)d_in[5];
    const float* bias    = (const float*)d_in[6];

    float* out = (float*)d_out;  // [N_NODES, D]
    float* rep;
    if ((long long)out_size >= 2LL * N_NODES * D) {
        rep = out + (size_t)N_NODES * D;
    } else {
        cudaGetSymbolAddress((void**)&rep, g_rep);
    }

    mix_kernel<<<1, 32>>>(linw);

    void* countPtr = nullptr;
    cudaGetSymbolAddress(&countPtr, g_count);
    cudaMemsetAsync(countPtr, 0, N_NODES * sizeof(int));

    tohalf_kernel<<<(N_NODES * D / 4 + 255) / 256, 256>>>((const float4*)input,
                                                          (const float4*)weight, bias);

    hist_kernel<<<(TOTAL_E + 255) / 256, 256>>>(adjrows);
    scan_pass1<<<SCAN_B, SCAN_T>>>();
    scan_pass2<<<1, 32>>>();
    scan_pass3<<<SCAN_B, SCAN_T>>>();
    fill_kernel<<<(TOTAL_E + 255) / 256, 256>>>(adjrows, adjcols, adjvals);

    // one warp per row
    long long gthreads = (long long)N_NODES * 32;
    gather_kernel<<<(int)((gthreads + 255) / 256), 256>>>(input, rep);

    gemm_wmma<<<(N_NODES + 63) / 64, 256>>>(out);
}

// round 17
// speedup vs baseline: 1.9587x; 1.0755x over previous
#include <cuda_runtime.h>
#include <cuda_fp16.h>
#include <mma.h>
using namespace nvcuda;

#define N_NODES 100000
#define D 128
#define N_ADJ 6
#define NNZ 600000
#define TOTAL_E (N_ADJ * NNZ)
#define N_HOPS 7
#define SPAD 144   // smem row width in halves (128 + 16): 288B rows, 32B-aligned frag ptrs

// multi-block scan geometry: 25 blocks x 1024 threads x 4 elems = 102400 >= 100000
#define SCAN_T 1024
#define SCAN_ELEMS (SCAN_T * 4)
#define SCAN_B ((N_NODES + SCAN_ELEMS - 1) / SCAN_ELEMS)

// ---------------- device scratch (static, no allocations) ----------------
__device__ int    g_count[N_NODES];
__device__ int    g_offsets[N_NODES + 1];
__device__ int    g_cursor[N_NODES];
__device__ int    g_bsum[SCAN_B];
__device__ int2   g_edges[TOTAL_E];            // (col, weight-as-int) per edge, CSR order
__device__ __half g_inph[(size_t)N_NODES * D]; // fp16 copy of input for gather
__device__ __half g_reph[((size_t)N_NODES + 64) * D]; // fp16 rep (+pad rows)
__device__ __half g_Wh[D * D];                 // fp16 copy of weight
__device__ float  g_biasrep[16 * D];           // bias replicated over 16 rows (acc init)
__device__ float  g_rep[(size_t)N_NODES * D];  // fallback if d_out lacks rep slot

// inline softmax of the 7 mixing weights (pure function of linw -> deterministic)
__device__ __forceinline__ float mix_weight(const float* __restrict__ lw, int i) {
    float m = lw[0];
    #pragma unroll
    for (int k = 1; k < N_HOPS; k++) m = fmaxf(m, lw[k]);
    float s = 0.f;
    #pragma unroll
    for (int k = 0; k < N_HOPS; k++) s += expf(lw[k] - m);
    return expf(lw[i] - m) / s;
}

// ---------------- prep: fp16 copies + bias replication + row histogram ----------------
// grid covers TOTAL_E threads; sub-ranges do the smaller jobs.
__global__ void prep_kernel(const float4* __restrict__ in, const float4* __restrict__ W,
                            const float* __restrict__ bias, const int* __restrict__ rows) {
    int i = blockIdx.x * blockDim.x + threadIdx.x;
    if (i < N_NODES * D / 4) {           // input -> fp16 (3.2M)
        float4 v = in[i];
        __half2 h0 = __floats2half2_rn(v.x, v.y);
        __half2 h1 = __floats2half2_rn(v.z, v.w);
        uint2 u;
        u.x = *reinterpret_cast<unsigned*>(&h0);
        u.y = *reinterpret_cast<unsigned*>(&h1);
        reinterpret_cast<uint2*>(g_inph)[i] = u;
    }
    if (i < D * D / 4) {                 // weight -> fp16 (4096)
        float4 v = W[i];
        __half2 h0 = __floats2half2_rn(v.x, v.y);
        __half2 h1 = __floats2half2_rn(v.z, v.w);
        uint2 u;
        u.x = *reinterpret_cast<unsigned*>(&h0);
        u.y = *reinterpret_cast<unsigned*>(&h1);
        reinterpret_cast<uint2*>(g_Wh)[i] = u;
    }
    if (i < 16 * D) {                    // bias replicated for acc init (2048)
        g_biasrep[i] = bias[i & (D - 1)];
    }
    if (i < TOTAL_E) {                   // row histogram (3.6M)
        atomicAdd(&g_count[rows[i]], 1);
    }
}

// ---------------- scan pass 1: per-block totals ----------------
__global__ __launch_bounds__(SCAN_T) void scan_pass1() {
    __shared__ int warp_sums[32];
    int t = threadIdx.x;
    int lane = t & 31, wid = t >> 5;
    int idx = blockIdx.x * SCAN_ELEMS + t * 4;

    int local = 0;
    if (idx + 3 < N_NODES) {
        int4 c = *reinterpret_cast<const int4*>(g_count + idx);
        local = c.x + c.y + c.z + c.w;
    } else {
        for (int j = 0; j < 4; j++)
            if (idx + j < N_NODES) local += g_count[idx + j];
    }
    #pragma unroll
    for (int d = 16; d > 0; d >>= 1) local += __shfl_down_sync(0xffffffffu, local, d);
    if (lane == 0) warp_sums[wid] = local;
    __syncthreads();
    if (wid == 0) {
        int v = warp_sums[lane];
        #pragma unroll
        for (int d = 16; d > 0; d >>= 1) v += __shfl_down_sync(0xffffffffu, v, d);
        if (lane == 0) g_bsum[blockIdx.x] = v;
    }
}

// ---------------- scan pass 3: block prefix (computed locally) + in-block scan ----------------
__global__ __launch_bounds__(SCAN_T) void scan_pass3() {
    __shared__ int warp_sums[32];
    __shared__ int s_bpre;
    int t = threadIdx.x;
    int lane = t & 31, wid = t >> 5;
    int idx = blockIdx.x * SCAN_ELEMS + t * 4;

    if (t == 0) {   // serial prefix of 25 block sums (trivial)
        int p = 0;
        for (int b = 0; b < (int)blockIdx.x; b++) p += g_bsum[b];
        s_bpre = p;
        if (blockIdx.x == 0) g_offsets[N_NODES] = TOTAL_E;
    }

    int4 c = make_int4(0, 0, 0, 0);
    if (idx + 3 < N_NODES) {
        c = *reinterpret_cast<const int4*>(g_count + idx);
    } else {
        if (idx + 0 < N_NODES) c.x = g_count[idx + 0];
        if (idx + 1 < N_NODES) c.y = g_count[idx + 1];
        if (idx + 2 < N_NODES) c.z = g_count[idx + 2];
        if (idx + 3 < N_NODES) c.w = g_count[idx + 3];
    }
    int local = c.x + c.y + c.z + c.w;

    int v = local;
    #pragma unroll
    for (int d = 1; d < 32; d <<= 1) {
        int n = __shfl_up_sync(0xffffffffu, v, d);
        if (lane >= d) v += n;
    }
    if (lane == 31) warp_sums[wid] = v;
    __syncthreads();
    if (wid == 0) {
        int w = warp_sums[lane];
        #pragma unroll
        for (int d = 1; d < 32; d <<= 1) {
            int n = __shfl_up_sync(0xffffffffu, w, d);
            if (lane >= d) w += n;
        }
        warp_sums[lane] = w;
    }
    __syncthreads();

    int warp_prefix = (wid > 0) ? warp_sums[wid - 1] : 0;
    int excl = s_bpre + warp_prefix + (v - local);
    int o0 = excl;
    int o1 = o0 + c.x;
    int o2 = o1 + c.y;
    int o3 = o2 + c.z;
    if (idx + 0 < N_NODES) { g_offsets[idx + 0] = o0; g_cursor[idx + 0] = o0; }
    if (idx + 1 < N_NODES) { g_offsets[idx + 1] = o1; g_cursor[idx + 1] = o1; }
    if (idx + 2 < N_NODES) { g_offsets[idx + 2] = o2; g_cursor[idx + 2] = o2; }
    if (idx + 3 < N_NODES) { g_offsets[idx + 3] = o3; g_cursor[idx + 3] = o3; }
}

// ---------------- fill: CSR scatter of (col, mix*val) ----------------
__global__ void fill_kernel(const int* __restrict__ rows,
                            const int* __restrict__ cols,
                            const float* __restrict__ vals,
                            const float* __restrict__ lw) {
    int e = blockIdx.x * blockDim.x + threadIdx.x;
    if (e >= TOTAL_E) return;
    int a = e / NNZ;
    int r = rows[e];
    int c = cols[e];
    float w = mix_weight(lw, a + 1) * vals[e];
    int slot = atomicAdd(&g_cursor[r], 1);
    g_edges[slot] = make_int2(c, __float_as_int(w));
}

// ---------------- gather: one warp per row; fp16 neighbors, fp32 acc, MLP=8 ----------------
__device__ __forceinline__ void gacc(float4& acc, float w, uint2 u) {
    __half2 h0 = *reinterpret_cast<__half2*>(&u.x);
    __half2 h1 = *reinterpret_cast<__half2*>(&u.y);
    float2 f0 = __half22float2(h0);
    float2 f1 = __half22float2(h1);
    acc.x = fmaf(w, f0.x, acc.x);
    acc.y = fmaf(w, f0.y, acc.y);
    acc.z = fmaf(w, f1.x, acc.z);
    acc.w = fmaf(w, f1.y, acc.w);
}

__global__ __launch_bounds__(256) void gather_kernel(const float* __restrict__ input,
                                                     const float* __restrict__ lw,
                                                     float* __restrict__ rep) {
    int gw = (blockIdx.x * blockDim.x + threadIdx.x) >> 5;  // global warp = row
    int lane = threadIdx.x & 31;
    if (gw >= N_NODES) return;
    int row = gw;

    float m0 = mix_weight(lw, 0);
    float4 acc = reinterpret_cast<const float4*>(input + (size_t)row * D)[lane];
    acc.x *= m0; acc.y *= m0; acc.z *= m0; acc.w *= m0;

    int beg = g_offsets[row];
    int end = g_offsets[row + 1];
    int e = beg;
    // 8x unrolled: 8 independent row-gathers in flight
    for (; e + 8 <= end; e += 8) {
        int2 ed[8];
        uint2 u[8];
        #pragma unroll
        for (int q = 0; q < 8; q++) ed[q] = __ldg(g_edges + e + q);
        #pragma unroll
        for (int q = 0; q < 8; q++)
            u[q] = __ldg(reinterpret_cast<const uint2*>(g_inph + (size_t)ed[q].x * D) + lane);
        #pragma unroll
        for (int q = 0; q < 8; q++) gacc(acc, __int_as_float(ed[q].y), u[q]);
    }
    for (; e < end; e++) {
        int2 ed = __ldg(g_edges + e);
        uint2 u = __ldg(reinterpret_cast<const uint2*>(g_inph + (size_t)ed.x * D) + lane);
        gacc(acc, __int_as_float(ed.y), u);
    }
    reinterpret_cast<float4*>(rep + (size_t)row * D)[lane] = acc;

    // fp16 copy for tensor GEMM
    __half2 h0 = __floats2half2_rn(acc.x, acc.y);
    __half2 h1 = __floats2half2_rn(acc.z, acc.w);
    uint2 uo;
    uo.x = *reinterpret_cast<unsigned*>(&h0);
    uo.y = *reinterpret_cast<unsigned*>(&h1);
    reinterpret_cast<uint2*>(g_reph + (size_t)row * D)[lane] = uo;
}

// ---------------- out = rep_f16 @ W_f16 + bias  (wmma, smem-staged) ----------------
__global__ __launch_bounds__(256) void gemm_wmma(float* __restrict__ out) {
    __shared__ __half Ws[D][SPAD];   // 128 x 144 halves = 36.9KB
    __shared__ __half As[64][SPAD];  // 64 x 144 halves = 18.4KB

    int tid = threadIdx.x;
    int w = tid >> 5;
    int rowBase = blockIdx.x * 64;

    // stage W (full 128x128): 2048 uint4, 8 per thread
    #pragma unroll
    for (int l = 0; l < 8; l++) {
        int i = tid + l * 256;
        int r = i >> 4;
        int c8 = (i & 15) * 8;
        uint4 v = *reinterpret_cast<const uint4*>(&g_Wh[r * D + c8]);
        *reinterpret_cast<uint4*>(&Ws[r][c8]) = v;
    }
    // stage A tile (64x128): 1024 uint4, 4 per thread (pad rows in g_reph)
    #pragma unroll
    for (int l = 0; l < 4; l++) {
        int i = tid + l * 256;
        int r = i >> 4;
        int c8 = (i & 15) * 8;
        uint4 v = *reinterpret_cast<const uint4*>(&g_reph[(size_t)(rowBase + r) * D + c8]);
        *reinterpret_cast<uint4*>(&As[r][c8]) = v;
    }
    __syncthreads();

    int rLoc = (w & 3) * 16;
    int colBase = (w >> 2) * 64;
    if (rowBase + rLoc + 16 <= N_NODES) {  // N_NODES % 16 == 0: frag fully in or out
        wmma::fragment<wmma::accumulator, 16, 16, 16, float> acc[4];
        #pragma unroll
        for (int j = 0; j < 4; j++)
            wmma::load_matrix_sync(acc[j], g_biasrep + colBase + j * 16, D,
                                   wmma::mem_row_major);

        wmma::fragment<wmma::matrix_a, 16, 16, 16, __half, wmma::row_major> af;
        wmma::fragment<wmma::matrix_b, 16, 16, 16, __half, wmma::row_major> bf;
        #pragma unroll
        for (int k = 0; k < D / 16; k++) {
            wmma::load_matrix_sync(af, &As[rLoc][k * 16], SPAD);
            #pragma unroll
            for (int j = 0; j < 4; j++) {
                wmma::load_matrix_sync(bf, &Ws[k * 16][colBase + j * 16], SPAD);
                wmma::mma_sync(acc[j], af, bf, acc[j]);
            }
        }
        #pragma unroll
        for (int j = 0; j < 4; j++)
            wmma::store_matrix_sync(out + (size_t)(rowBase + rLoc) * D + colBase + j * 16,
                                    acc[j], D, wmma::mem_row_major);
    }
}

extern "C" void kernel_launch(void* const* d_in, const int* in_sizes, int n_in,
                              void* d_out, int out_size) {
    const float* input   = (const float*)d_in[0];
    const int*   adjrows = (const int*)d_in[1];   // jnp int64 -> int32 (x64 off)
    const int*   adjcols = (const int*)d_in[2];
    const float* adjvals = (const float*)d_in[3];
    const float* weight  = (const float*)d_in[4];
    const float* linw    = (const float*)d_in[5];
    const float* bias    = (const float*)d_in[6];

    float* out = (float*)d_out;  // [N_NODES, D]
    float* rep;
    if ((long long)out_size >= 2LL * N_NODES * D) {
        rep = out + (size_t)N_NODES * D;
    } else {
        cudaGetSymbolAddress((void**)&rep, g_rep);
    }

    void* countPtr = nullptr;
    cudaGetSymbolAddress(&countPtr, g_count);
    cudaMemsetAsync(countPtr, 0, N_NODES * sizeof(int));

    // fused fp16 conversion + bias replication + row histogram
    prep_kernel<<<(TOTAL_E + 255) / 256, 256>>>((const float4*)input,
                                                (const float4*)weight, bias, adjrows);
    scan_pass1<<<SCAN_B, SCAN_T>>>();
    scan_pass3<<<SCAN_B, SCAN_T>>>();
    fill_kernel<<<(TOTAL_E + 255) / 256, 256>>>(adjrows, adjcols, adjvals, linw);

    // one warp per row
    long long gthreads = (long long)N_NODES * 32;
    gather_kernel<<<(int)((gthreads + 255) / 256), 256>>>(input, linw, rep);

    gemm_wmma<<<(N_NODES + 63) / 64, 256>>>(out);
}